// round 9
// baseline (speedup 1.0000x reference)
#include <cuda_runtime.h>
#include <cuda_bf16.h>
#include <cstdint>
#include <math.h>

#define BATCH 4
#define SEQ   2048
#define DMODEL 1024

// CTA tile 256(M) x 128(N), BK=64 -> 128B rows.
// Stage layout: A_hi(32K) | A_lo(32K) | B_hi(16K) | B_lo(16K) = 96KB
#define A_PLANE 32768
#define B_PLANE 16384
#define OFF_BH_S (2 * A_PLANE)            // 65536
#define STAGE_BYTES (2 * A_PLANE + 2 * B_PLANE)   // 98304
#define NSTAGE 2
#define SMEM_TOTAL (NSTAGE * STAGE_BYTES)         // 192KB
#define NTHREADS 512

// ======================= scratch (hi/lo bf16 planes) ========================
__device__ __align__(16) __nv_bfloat16 g_Eh[BATCH * SEQ * DMODEL];
__device__ __align__(16) __nv_bfloat16 g_El[BATCH * SEQ * DMODEL];
__device__ __align__(16) __nv_bfloat16 g_Wh[3 * DMODEL * DMODEL];
__device__ __align__(16) __nv_bfloat16 g_Wl[3 * DMODEL * DMODEL];
__device__ __align__(16) __nv_bfloat16 g_Qh[BATCH * SEQ * DMODEL];
__device__ __align__(16) __nv_bfloat16 g_Ql[BATCH * SEQ * DMODEL];
__device__ __align__(16) __nv_bfloat16 g_Kh[BATCH * SEQ * DMODEL];
__device__ __align__(16) __nv_bfloat16 g_Kl[BATCH * SEQ * DMODEL];
__device__ __align__(16) __nv_bfloat16 g_Vth[BATCH * DMODEL * SEQ];  // [b][d][s]
__device__ __align__(16) __nv_bfloat16 g_Vtl[BATCH * DMODEL * SEQ];
__device__ __align__(16) __nv_bfloat16 g_Ph[BATCH * SEQ * SEQ];
__device__ __align__(16) __nv_bfloat16 g_Pl[BATCH * SEQ * SEQ];
__device__ float g_mags[BATCH * SEQ];
__device__ float g_thresh;

__device__ __forceinline__ void split_f32(float x, unsigned short& h, unsigned short& l) {
    __nv_bfloat16 hb = __float2bfloat16(x);
    float hf = __bfloat162float(hb);
    __nv_bfloat16 lb = __float2bfloat16(x - hf);
    h = __bfloat16_as_ushort(hb);
    l = __bfloat16_as_ushort(lb);
}

__device__ __forceinline__ uint32_t smem_u32(const void* p) {
    uint32_t a;
    asm("{ .reg .u64 t; cvta.to.shared.u64 t, %1; cvt.u32.u64 %0, t; }" : "=r"(a) : "l"(p));
    return a;
}

__device__ __forceinline__ void cp16(uint32_t dst, const void* src) {
    asm volatile("cp.async.cg.shared.global [%0], [%1], 16;" :: "r"(dst), "l"(src));
}
#define CP_COMMIT() asm volatile("cp.async.commit_group;" ::: "memory")
__device__ __forceinline__ void cp_wait(int rem) {
    if (rem >= 1) asm volatile("cp.async.wait_group 1;" ::: "memory");
    else          asm volatile("cp.async.wait_group 0;" ::: "memory");
}

__device__ __forceinline__ void ldm4(uint32_t f[4], uint32_t addr) {
    asm volatile("ldmatrix.sync.aligned.m8n8.x4.shared.b16 {%0,%1,%2,%3}, [%4];"
        : "=r"(f[0]), "=r"(f[1]), "=r"(f[2]), "=r"(f[3]) : "r"(addr));
}

__device__ __forceinline__ void mma16816(float c[4], const uint32_t a[4],
                                         uint32_t b0, uint32_t b1) {
    asm volatile(
        "mma.sync.aligned.m16n8k16.row.col.f32.bf16.bf16.f32 "
        "{%0,%1,%2,%3}, {%4,%5,%6,%7}, {%8,%9}, {%0,%1,%2,%3};"
        : "+f"(c[0]), "+f"(c[1]), "+f"(c[2]), "+f"(c[3])
        : "r"(a[0]), "r"(a[1]), "r"(a[2]), "r"(a[3]), "r"(b0), "r"(b1));
}

// ======================= small kernels ======================================
__global__ void convert_kernel(const float* __restrict__ src, int which, int n4) {
    int i = blockIdx.x * blockDim.x + threadIdx.x;
    if (i >= n4) return;
    __nv_bfloat16* H = (which == 0) ? g_Eh : g_Wh + (size_t)(which - 1) * DMODEL * DMODEL;
    __nv_bfloat16* L = (which == 0) ? g_El : g_Wl + (size_t)(which - 1) * DMODEL * DMODEL;
    float4 v = ((const float4*)src)[i];
    unsigned short h0, h1, h2, h3, l0, l1, l2, l3;
    split_f32(v.x, h0, l0); split_f32(v.y, h1, l1);
    split_f32(v.z, h2, l2); split_f32(v.w, h3, l3);
    *(uint2*)(H + (size_t)i * 4) = make_uint2((uint32_t)h0 | ((uint32_t)h1 << 16),
                                              (uint32_t)h2 | ((uint32_t)h3 << 16));
    *(uint2*)(L + (size_t)i * 4) = make_uint2((uint32_t)l0 | ((uint32_t)l1 << 16),
                                              (uint32_t)l2 | ((uint32_t)l3 << 16));
}

__global__ void mags_kernel(const float* __restrict__ E) {
    int row = blockIdx.x;
    const float4* p = (const float4*)(E + (size_t)row * DMODEL);
    int tid = threadIdx.x;
    float4 v = p[tid];
    float s = v.x * v.x + v.y * v.y + v.z * v.z + v.w * v.w;
    __shared__ float sm[256];
    sm[tid] = s;
    __syncthreads();
    for (int off = 128; off > 0; off >>= 1) {
        if (tid < off) sm[tid] += sm[tid + off];
        __syncthreads();
    }
    if (tid == 0) g_mags[row] = sqrtf(sm[0]);
}

__global__ void thresh_kernel() {
    int tid = threadIdx.x;
    __shared__ double sd[256];
    double total = 0.0;
    for (int b = 0; b < BATCH; b++) {
        double local = 0.0;
        for (int i = tid; i < SEQ; i += 256) local += (double)g_mags[b * SEQ + i];
        sd[tid] = local;
        __syncthreads();
        for (int off = 128; off > 0; off >>= 1) {
            if (tid < off) sd[tid] += sd[tid + off];
            __syncthreads();
        }
        if (tid == 0) total += sd[0] * sd[0];
        __syncthreads();
    }
    if (tid == 0) g_thresh = (float)(total / ((double)BATCH * SEQ * SEQ));
}

__global__ void softmax_kernel(float* __restrict__ w) {
    size_t row = blockIdx.x;
    float4* p = (float4*)(w + row * SEQ);
    int tid = threadIdx.x;
    float4 v0 = p[tid];
    float4 v1 = p[tid + 256];
    float m = fmaxf(fmaxf(fmaxf(v0.x, v0.y), fmaxf(v0.z, v0.w)),
                    fmaxf(fmaxf(v1.x, v1.y), fmaxf(v1.z, v1.w)));
    __shared__ float sm[256];
    sm[tid] = m;
    __syncthreads();
    for (int off = 128; off > 0; off >>= 1) {
        if (tid < off) sm[tid] = fmaxf(sm[tid], sm[tid + off]);
        __syncthreads();
    }
    m = sm[0];
    __syncthreads();
    v0.x = expf(v0.x - m); v0.y = expf(v0.y - m);
    v0.z = expf(v0.z - m); v0.w = expf(v0.w - m);
    v1.x = expf(v1.x - m); v1.y = expf(v1.y - m);
    v1.z = expf(v1.z - m); v1.w = expf(v1.w - m);
    float s = v0.x + v0.y + v0.z + v0.w + v1.x + v1.y + v1.z + v1.w;
    sm[tid] = s;
    __syncthreads();
    for (int off = 128; off > 0; off >>= 1) {
        if (tid < off) sm[tid] += sm[tid + off];
        __syncthreads();
    }
    float inv = 1.0f / sm[0];
    v0.x *= inv; v0.y *= inv; v0.z *= inv; v0.w *= inv;
    v1.x *= inv; v1.y *= inv; v1.z *= inv; v1.w *= inv;
    p[tid] = v0;
    p[tid + 256] = v1;

    unsigned short h[4], l[4];
    size_t b0 = row * SEQ + (size_t)tid * 4;
    split_f32(v0.x, h[0], l[0]); split_f32(v0.y, h[1], l[1]);
    split_f32(v0.z, h[2], l[2]); split_f32(v0.w, h[3], l[3]);
    *(uint2*)(g_Ph + b0) = make_uint2((uint32_t)h[0] | ((uint32_t)h[1] << 16),
                                      (uint32_t)h[2] | ((uint32_t)h[3] << 16));
    *(uint2*)(g_Pl + b0) = make_uint2((uint32_t)l[0] | ((uint32_t)l[1] << 16),
                                      (uint32_t)l[2] | ((uint32_t)l[3] << 16));
    size_t b1 = row * SEQ + (size_t)(tid + 256) * 4;
    split_f32(v1.x, h[0], l[0]); split_f32(v1.y, h[1], l[1]);
    split_f32(v1.z, h[2], l[2]); split_f32(v1.w, h[3], l[3]);
    *(uint2*)(g_Ph + b1) = make_uint2((uint32_t)h[0] | ((uint32_t)h[1] << 16),
                                      (uint32_t)h[2] | ((uint32_t)h[3] << 16));
    *(uint2*)(g_Pl + b1) = make_uint2((uint32_t)l[0] | ((uint32_t)l[1] << 16),
                                      (uint32_t)l[2] | ((uint32_t)l[3] << 16));
}

// ======================= pipelined HMMA GEMM core ===========================
// C[256x128]/CTA, 16 warps (4m x 4n) each 64x32, BK=64, 2-stage cp.async ring.
__device__ __forceinline__ void load_stage(
    uint32_t sb, int slot, int tid,
    const __nv_bfloat16* __restrict__ Ah, const __nv_bfloat16* __restrict__ Al,
    const __nv_bfloat16* __restrict__ Bh, const __nv_bfloat16* __restrict__ Bl,
    int lda, int ldb, int m0, int n0, int k0)
{
    uint32_t st = sb + (uint32_t)slot * STAGE_BYTES;
    // A: 256 rows, 2 threads/row, 4 segs x 2 planes each
    {
        int row = tid >> 1, hs = tid & 1;
        const __nv_bfloat16* a  = Ah + (size_t)(m0 + row) * lda + k0;
        const __nv_bfloat16* al = Al + (size_t)(m0 + row) * lda + k0;
        uint32_t d = st + (uint32_t)row * 128;
        #pragma unroll
        for (int i = 0; i < 4; i++) {
            int seg = hs * 4 + i;
            uint32_t sw = (uint32_t)((seg ^ (row & 7)) * 16);
            cp16(d + sw,           a + seg * 8);
            cp16(d + sw + A_PLANE, al + seg * 8);
        }
    }
    // B: 128 rows, 4 threads/row, 2 segs x 2 planes each
    {
        int row = tid >> 2, qs = tid & 3;
        const __nv_bfloat16* b  = Bh + (size_t)(n0 + row) * ldb + k0;
        const __nv_bfloat16* bl = Bl + (size_t)(n0 + row) * ldb + k0;
        uint32_t d = st + OFF_BH_S + (uint32_t)row * 128;
        #pragma unroll
        for (int i = 0; i < 2; i++) {
            int seg = qs * 2 + i;
            uint32_t sw = (uint32_t)((seg ^ (row & 7)) * 16);
            cp16(d + sw,           b + seg * 8);
            cp16(d + sw + B_PLANE, bl + seg * 8);
        }
    }
}

__device__ __forceinline__ void gemm_run(
    const __nv_bfloat16* __restrict__ Ah, const __nv_bfloat16* __restrict__ Al,
    const __nv_bfloat16* __restrict__ Bh, const __nv_bfloat16* __restrict__ Bl,
    int lda, int ldb, int K, int m0, int n0, float acc[4][4][4])
{
    extern __shared__ __align__(16) char smem[];
    uint32_t sb = smem_u32(smem);
    int tid = threadIdx.x, lane = tid & 31, warp = tid >> 5;
    int wm = (warp >> 2) * 64, wn = (warp & 3) * 32;
    int g = lane >> 3, r = lane & 7;
    int rb = (g & 1) * 8 + r, hsel = g >> 1;

    int NC = K >> 6;
    #pragma unroll
    for (int s = 0; s < NSTAGE; s++) {
        load_stage(sb, s, tid, Ah, Al, Bh, Bl, lda, ldb, m0, n0, s * 64);
        CP_COMMIT();
    }

    uint32_t arow = (uint32_t)((wm + rb) * 128);
    uint32_t brow = (uint32_t)((wn + rb) * 128) + OFF_BH_S;

    for (int c = 0; c < NC; c++) {
        int rem = NC - 1 - c;
        cp_wait(rem < 1 ? rem : 1);
        __syncthreads();
        uint32_t st = sb + (uint32_t)(c & 1) * STAGE_BYTES;
        #pragma unroll
        for (int kb = 0; kb < 4; kb++) {
            uint32_t segoff = (uint32_t)((((kb * 2) | hsel) ^ r) * 16);
            uint32_t bh[2][4], bl[2][4];
            #pragma unroll
            for (int nb = 0; nb < 2; nb++) {
                uint32_t bd = st + brow + (uint32_t)(nb * 16 * 128) + segoff;
                ldm4(bh[nb], bd);
                ldm4(bl[nb], bd + B_PLANE);
            }
            #pragma unroll
            for (int mh = 0; mh < 2; mh++) {
                uint32_t ah[2][4], al[2][4];
                #pragma unroll
                for (int mi = 0; mi < 2; mi++) {
                    uint32_t ad = st + arow + (uint32_t)((mh * 2 + mi) * 16 * 128) + segoff;
                    ldm4(ah[mi], ad);
                    ldm4(al[mi], ad + A_PLANE);
                }
                #pragma unroll
                for (int mi = 0; mi < 2; mi++)
                    #pragma unroll
                    for (int nb = 0; nb < 2; nb++)
                        #pragma unroll
                        for (int s = 0; s < 2; s++) {
                            int ni = nb * 2 + s;
                            float* a4 = acc[mh * 2 + mi][ni];
                            mma16816(a4, ah[mi], bh[nb][s], bh[nb][s + 2]);
                            mma16816(a4, ah[mi], bl[nb][s], bl[nb][s + 2]);
                            mma16816(a4, al[mi], bh[nb][s], bh[nb][s + 2]);
                        }
            }
        }
        __syncthreads();
        if (c + NSTAGE < NC) {
            load_stage(sb, c & 1, tid, Ah, Al, Bh, Bl, lda, ldb, m0, n0,
                       (c + NSTAGE) * 64);
            CP_COMMIT();
        }
    }
}

// ======================= GEMM kernels =======================================
__global__ void __launch_bounds__(NTHREADS, 1) qkv_tc() {
    int z = blockIdx.z;
    const __nv_bfloat16* Bwh = g_Wh + (size_t)z * DMODEL * DMODEL;
    const __nv_bfloat16* Bwl = g_Wl + (size_t)z * DMODEL * DMODEL;
    int m0 = blockIdx.y * 256, n0 = blockIdx.x * 128;
    float acc[4][4][4] = {};
    gemm_run(g_Eh, g_El, Bwh, Bwl, DMODEL, DMODEL, DMODEL, m0, n0, acc);

    int lane = threadIdx.x & 31, warp = threadIdx.x >> 5;
    int wm = (warp >> 2) * 64, wn = (warp & 3) * 32;
    #pragma unroll
    for (int mi = 0; mi < 4; mi++)
        #pragma unroll
        for (int h = 0; h < 2; h++) {
            int rg = m0 + wm + mi * 16 + h * 8 + (lane >> 2);
            #pragma unroll
            for (int ni = 0; ni < 4; ni++) {
                int col = n0 + wn + ni * 8 + (lane & 3) * 2;
                unsigned short h0, h1, l0, l1;
                split_f32(acc[mi][ni][h * 2], h0, l0);
                split_f32(acc[mi][ni][h * 2 + 1], h1, l1);
                if (z == 2) {
                    int b = rg >> 11, s = rg & (SEQ - 1);
                    size_t vb = (size_t)b * DMODEL * SEQ;
                    g_Vth[vb + (size_t)col * SEQ + s] = __ushort_as_bfloat16(h0);
                    g_Vth[vb + (size_t)(col + 1) * SEQ + s] = __ushort_as_bfloat16(h1);
                    g_Vtl[vb + (size_t)col * SEQ + s] = __ushort_as_bfloat16(l0);
                    g_Vtl[vb + (size_t)(col + 1) * SEQ + s] = __ushort_as_bfloat16(l1);
                } else {
                    __nv_bfloat16* Ch = (z == 0) ? g_Qh : g_Kh;
                    __nv_bfloat16* Cl = (z == 0) ? g_Ql : g_Kl;
                    *(uint32_t*)&Ch[(size_t)rg * DMODEL + col] =
                        (uint32_t)h0 | ((uint32_t)h1 << 16);
                    *(uint32_t*)&Cl[(size_t)rg * DMODEL + col] =
                        (uint32_t)l0 | ((uint32_t)l1 << 16);
                }
            }
        }
}

__global__ void __launch_bounds__(NTHREADS, 1) scores_tc(
    const float* __restrict__ intent_bias, const int* __restrict__ mask,
    float* __restrict__ wts)
{
    int b = blockIdx.z;
    size_t off = (size_t)b * SEQ * DMODEL;
    int m0 = blockIdx.y * 256, n0 = blockIdx.x * 128;
    float acc[4][4][4] = {};
    gemm_run(g_Qh + off, g_Ql + off, g_Kh + off, g_Kl + off,
             DMODEL, DMODEL, DMODEL, m0, n0, acc);

    int lane = threadIdx.x & 31, warp = threadIdx.x >> 5;
    int wm = (warp >> 2) * 64, wn = (warp & 3) * 32;
    float th = g_thresh;
    float bias = intent_bias[0];
    #pragma unroll
    for (int mi = 0; mi < 4; mi++)
        #pragma unroll
        for (int h = 0; h < 2; h++) {
            int q = m0 + wm + mi * 16 + h * 8 + (lane >> 2);
            float mq = g_mags[b * SEQ + q];
            size_t rb = ((size_t)b * SEQ + q) * SEQ;
            #pragma unroll
            for (int ni = 0; ni < 4; ni++) {
                int col = n0 + wn + ni * 8 + (lane & 3) * 2;
                float x0 = acc[mi][ni][h * 2] * 0.03125f;
                float x1 = acc[mi][ni][h * 2 + 1] * 0.03125f;
                float mk0 = g_mags[b * SEQ + col];
                float mk1 = g_mags[b * SEQ + col + 1];
                if (mq * mk0 > th) x0 += bias;
                if (mq * mk1 > th) x1 += bias;
                int2 mv = *(const int2*)&mask[rb + col];
                if (mv.x == 0) x0 = -1e9f;
                if (mv.y == 0) x1 = -1e9f;
                *(float2*)&wts[rb + col] = make_float2(x0, x1);
            }
        }
}

__global__ void __launch_bounds__(NTHREADS, 1) av_tc(float* __restrict__ att) {
    int b = blockIdx.z;
    size_t po = (size_t)b * SEQ * SEQ;
    size_t vo = (size_t)b * DMODEL * SEQ;
    int m0 = blockIdx.y * 256, n0 = blockIdx.x * 128;
    float acc[4][4][4] = {};
    gemm_run(g_Ph + po, g_Pl + po, g_Vth + vo, g_Vtl + vo,
             SEQ, SEQ, SEQ, m0, n0, acc);

    int lane = threadIdx.x & 31, warp = threadIdx.x >> 5;
    int wm = (warp >> 2) * 64, wn = (warp & 3) * 32;
    #pragma unroll
    for (int mi = 0; mi < 4; mi++)
        #pragma unroll
        for (int h = 0; h < 2; h++) {
            int s = m0 + wm + mi * 16 + h * 8 + (lane >> 2);
            #pragma unroll
            for (int ni = 0; ni < 4; ni++) {
                int col = n0 + wn + ni * 8 + (lane & 3) * 2;
                *(float2*)&att[((size_t)b * SEQ + s) * DMODEL + col] =
                    make_float2(acc[mi][ni][h * 2], acc[mi][ni][h * 2 + 1]);
            }
        }
}

// ======================= launch =============================================
extern "C" void kernel_launch(void* const* d_in, const int* in_sizes, int n_in,
                              void* d_out, int out_size)
{
    (void)in_sizes; (void)n_in; (void)out_size;
    const float* E    = (const float*)d_in[0];
    const float* Wq   = (const float*)d_in[1];
    const float* Wk   = (const float*)d_in[2];
    const float* Wv   = (const float*)d_in[3];
    const float* bias = (const float*)d_in[4];
    const int*   mask = (const int*)d_in[5];

    float* out = (float*)d_out;
    float* att = out;                                  // [B,S,D]
    float* wts = out + (size_t)BATCH * SEQ * DMODEL;   // [B,S,S]

    cudaFuncSetAttribute(qkv_tc,    cudaFuncAttributeMaxDynamicSharedMemorySize, SMEM_TOTAL);
    cudaFuncSetAttribute(scores_tc, cudaFuncAttributeMaxDynamicSharedMemorySize, SMEM_TOTAL);
    cudaFuncSetAttribute(av_tc,     cudaFuncAttributeMaxDynamicSharedMemorySize, SMEM_TOTAL);

    convert_kernel<<<(BATCH * SEQ * DMODEL / 4 + 255) / 256, 256>>>(E, 0, BATCH * SEQ * DMODEL / 4);
    convert_kernel<<<(DMODEL * DMODEL / 4 + 255) / 256, 256>>>(Wq, 1, DMODEL * DMODEL / 4);
    convert_kernel<<<(DMODEL * DMODEL / 4 + 255) / 256, 256>>>(Wk, 2, DMODEL * DMODEL / 4);
    convert_kernel<<<(DMODEL * DMODEL / 4 + 255) / 256, 256>>>(Wv, 3, DMODEL * DMODEL / 4);

    mags_kernel<<<BATCH * SEQ, 256>>>(E);
    thresh_kernel<<<1, 256>>>();

    dim3 gQKV(DMODEL / 128, (BATCH * SEQ) / 256, 3);
    qkv_tc<<<gQKV, NTHREADS, SMEM_TOTAL>>>();

    dim3 gS(SEQ / 128, SEQ / 256, BATCH);
    scores_tc<<<gS, NTHREADS, SMEM_TOTAL>>>(bias, mask, wts);

    softmax_kernel<<<BATCH * SEQ, 256>>>(wts);

    dim3 gAV(DMODEL / 128, SEQ / 256, BATCH);
    av_tc<<<gAV, NTHREADS, SMEM_TOTAL>>>(att);
}

// round 10
// speedup vs baseline: 1.1226x; 1.1226x over previous
#include <cuda_runtime.h>
#include <cuda_bf16.h>
#include <cstdint>
#include <math.h>

#define BATCH 4
#define SEQ   2048
#define DMODEL 1024

// smem geometry: BK=64 bf16 -> 128B rows; 4 planes (Ah,Al,Bh,Bl) per stage
#define PLANE_BYTES  16384                  // 128 rows * 128B
#define STAGE_BYTES  (4 * PLANE_BYTES)      // 64KB
#define NSTAGE       3
#define SMEM_TOTAL   (NSTAGE * STAGE_BYTES) // 192KB
#define NTHREADS     512

// ======================= scratch (hi/lo bf16 planes) ========================
__device__ __align__(16) __nv_bfloat16 g_Eh[BATCH * SEQ * DMODEL];
__device__ __align__(16) __nv_bfloat16 g_El[BATCH * SEQ * DMODEL];
__device__ __align__(16) __nv_bfloat16 g_Wh[3 * DMODEL * DMODEL];
__device__ __align__(16) __nv_bfloat16 g_Wl[3 * DMODEL * DMODEL];
__device__ __align__(16) __nv_bfloat16 g_Qh[BATCH * SEQ * DMODEL];
__device__ __align__(16) __nv_bfloat16 g_Ql[BATCH * SEQ * DMODEL];
__device__ __align__(16) __nv_bfloat16 g_Kh[BATCH * SEQ * DMODEL];
__device__ __align__(16) __nv_bfloat16 g_Kl[BATCH * SEQ * DMODEL];
__device__ __align__(16) __nv_bfloat16 g_Vth[BATCH * DMODEL * SEQ];  // [b][d][s]
__device__ __align__(16) __nv_bfloat16 g_Vtl[BATCH * DMODEL * SEQ];
__device__ __align__(16) __nv_bfloat16 g_Ph[BATCH * SEQ * SEQ];
__device__ __align__(16) __nv_bfloat16 g_Pl[BATCH * SEQ * SEQ];
__device__ float g_mags[BATCH * SEQ];
__device__ float g_thresh;

__device__ __forceinline__ void split_f32(float x, unsigned short& h, unsigned short& l) {
    __nv_bfloat16 hb = __float2bfloat16(x);
    float hf = __bfloat162float(hb);
    __nv_bfloat16 lb = __float2bfloat16(x - hf);
    h = __bfloat16_as_ushort(hb);
    l = __bfloat16_as_ushort(lb);
}

__device__ __forceinline__ uint32_t smem_u32(const void* p) {
    uint32_t a;
    asm("{ .reg .u64 t; cvta.to.shared.u64 t, %1; cvt.u32.u64 %0, t; }" : "=r"(a) : "l"(p));
    return a;
}

__device__ __forceinline__ void cp16(uint32_t dst, const void* src) {
    asm volatile("cp.async.cg.shared.global [%0], [%1], 16;" :: "r"(dst), "l"(src));
}
#define CP_COMMIT() asm volatile("cp.async.commit_group;" ::: "memory")
#define CP_WAIT1()  asm volatile("cp.async.wait_group 1;" ::: "memory")

__device__ __forceinline__ void ldm4(uint32_t f[4], uint32_t addr) {
    asm volatile("ldmatrix.sync.aligned.m8n8.x4.shared.b16 {%0,%1,%2,%3}, [%4];"
        : "=r"(f[0]), "=r"(f[1]), "=r"(f[2]), "=r"(f[3]) : "r"(addr));
}

__device__ __forceinline__ void mma16816(float c[4], const uint32_t a[4],
                                         uint32_t b0, uint32_t b1) {
    asm volatile(
        "mma.sync.aligned.m16n8k16.row.col.f32.bf16.bf16.f32 "
        "{%0,%1,%2,%3}, {%4,%5,%6,%7}, {%8,%9}, {%0,%1,%2,%3};"
        : "+f"(c[0]), "+f"(c[1]), "+f"(c[2]), "+f"(c[3])
        : "r"(a[0]), "r"(a[1]), "r"(a[2]), "r"(a[3]), "r"(b0), "r"(b1));
}

// ======================= small kernels ======================================
// One launch converts E + Wq + Wk + Wv into hi/lo planes.
#define NE4 (BATCH * SEQ * DMODEL / 4)
#define NW4 (DMODEL * DMODEL / 4)
__global__ void convert_all(const float* __restrict__ E,
                            const float* __restrict__ Wq,
                            const float* __restrict__ Wk,
                            const float* __restrict__ Wv)
{
    int i = blockIdx.x * blockDim.x + threadIdx.x;
    const float* src;
    __nv_bfloat16 *H, *L;
    int j;
    if (i < NE4) {
        src = E; H = g_Eh; L = g_El; j = i;
    } else if (i < NE4 + NW4) {
        src = Wq; H = g_Wh; L = g_Wl; j = i - NE4;
    } else if (i < NE4 + 2 * NW4) {
        src = Wk; H = g_Wh + (size_t)DMODEL * DMODEL; L = g_Wl + (size_t)DMODEL * DMODEL;
        j = i - NE4 - NW4;
    } else if (i < NE4 + 3 * NW4) {
        src = Wv; H = g_Wh + 2 * (size_t)DMODEL * DMODEL; L = g_Wl + 2 * (size_t)DMODEL * DMODEL;
        j = i - NE4 - 2 * NW4;
    } else return;
    float4 v = ((const float4*)src)[j];
    unsigned short h0, h1, h2, h3, l0, l1, l2, l3;
    split_f32(v.x, h0, l0); split_f32(v.y, h1, l1);
    split_f32(v.z, h2, l2); split_f32(v.w, h3, l3);
    *(uint2*)(H + (size_t)j * 4) = make_uint2((uint32_t)h0 | ((uint32_t)h1 << 16),
                                              (uint32_t)h2 | ((uint32_t)h3 << 16));
    *(uint2*)(L + (size_t)j * 4) = make_uint2((uint32_t)l0 | ((uint32_t)l1 << 16),
                                              (uint32_t)l2 | ((uint32_t)l3 << 16));
}

__global__ void mags_kernel(const float* __restrict__ E) {
    int row = blockIdx.x;
    const float4* p = (const float4*)(E + (size_t)row * DMODEL);
    int tid = threadIdx.x;
    float4 v = p[tid];
    float s = v.x * v.x + v.y * v.y + v.z * v.z + v.w * v.w;
    __shared__ float sm[256];
    sm[tid] = s;
    __syncthreads();
    for (int off = 128; off > 0; off >>= 1) {
        if (tid < off) sm[tid] += sm[tid + off];
        __syncthreads();
    }
    if (tid == 0) g_mags[row] = sqrtf(sm[0]);
}

__global__ void thresh_kernel() {
    int tid = threadIdx.x;
    __shared__ double sd[256];
    double total = 0.0;
    for (int b = 0; b < BATCH; b++) {
        double local = 0.0;
        for (int i = tid; i < SEQ; i += 256) local += (double)g_mags[b * SEQ + i];
        sd[tid] = local;
        __syncthreads();
        for (int off = 128; off > 0; off >>= 1) {
            if (tid < off) sd[tid] += sd[tid + off];
            __syncthreads();
        }
        if (tid == 0) total += sd[0] * sd[0];
        __syncthreads();
    }
    if (tid == 0) g_thresh = (float)(total / ((double)BATCH * SEQ * SEQ));
}

__global__ void softmax_kernel(float* __restrict__ w) {
    size_t row = blockIdx.x;
    float4* p = (float4*)(w + row * SEQ);
    int tid = threadIdx.x;
    float4 v0 = p[tid];
    float4 v1 = p[tid + 256];
    float m = fmaxf(fmaxf(fmaxf(v0.x, v0.y), fmaxf(v0.z, v0.w)),
                    fmaxf(fmaxf(v1.x, v1.y), fmaxf(v1.z, v1.w)));
    __shared__ float sm[256];
    sm[tid] = m;
    __syncthreads();
    for (int off = 128; off > 0; off >>= 1) {
        if (tid < off) sm[tid] = fmaxf(sm[tid], sm[tid + off]);
        __syncthreads();
    }
    m = sm[0];
    __syncthreads();
    v0.x = expf(v0.x - m); v0.y = expf(v0.y - m);
    v0.z = expf(v0.z - m); v0.w = expf(v0.w - m);
    v1.x = expf(v1.x - m); v1.y = expf(v1.y - m);
    v1.z = expf(v1.z - m); v1.w = expf(v1.w - m);
    float s = v0.x + v0.y + v0.z + v0.w + v1.x + v1.y + v1.z + v1.w;
    sm[tid] = s;
    __syncthreads();
    for (int off = 128; off > 0; off >>= 1) {
        if (tid < off) sm[tid] += sm[tid + off];
        __syncthreads();
    }
    float inv = 1.0f / sm[0];
    v0.x *= inv; v0.y *= inv; v0.z *= inv; v0.w *= inv;
    v1.x *= inv; v1.y *= inv; v1.z *= inv; v1.w *= inv;
    p[tid] = v0;
    p[tid + 256] = v1;

    unsigned short h[4], l[4];
    size_t b0 = row * SEQ + (size_t)tid * 4;
    split_f32(v0.x, h[0], l[0]); split_f32(v0.y, h[1], l[1]);
    split_f32(v0.z, h[2], l[2]); split_f32(v0.w, h[3], l[3]);
    *(uint2*)(g_Ph + b0) = make_uint2((uint32_t)h[0] | ((uint32_t)h[1] << 16),
                                      (uint32_t)h[2] | ((uint32_t)h[3] << 16));
    *(uint2*)(g_Pl + b0) = make_uint2((uint32_t)l[0] | ((uint32_t)l[1] << 16),
                                      (uint32_t)l[2] | ((uint32_t)l[3] << 16));
    size_t b1 = row * SEQ + (size_t)(tid + 256) * 4;
    split_f32(v1.x, h[0], l[0]); split_f32(v1.y, h[1], l[1]);
    split_f32(v1.z, h[2], l[2]); split_f32(v1.w, h[3], l[3]);
    *(uint2*)(g_Ph + b1) = make_uint2((uint32_t)h[0] | ((uint32_t)h[1] << 16),
                                      (uint32_t)h[2] | ((uint32_t)h[3] << 16));
    *(uint2*)(g_Pl + b1) = make_uint2((uint32_t)l[0] | ((uint32_t)l[1] << 16),
                                      (uint32_t)l[2] | ((uint32_t)l[3] << 16));
}

// ======================= pipelined HMMA GEMM core ===========================
// C[128x128]/CTA, 16 warps (4x4) each 32x32, BK=64, 3-stage ring,
// single __syncthreads per chunk (loads issued post-sync -> no WAR hazard).
__device__ __forceinline__ void load_stage(
    uint32_t sb, int slot, int row, int qs,
    const __nv_bfloat16* __restrict__ Ah, const __nv_bfloat16* __restrict__ Al,
    const __nv_bfloat16* __restrict__ Bh, const __nv_bfloat16* __restrict__ Bl,
    int lda, int ldb, int m0, int n0, int k0)
{
    uint32_t drow = sb + (uint32_t)slot * STAGE_BYTES + (uint32_t)row * 128;
    const __nv_bfloat16* a  = Ah + (size_t)(m0 + row) * lda + k0;
    const __nv_bfloat16* al = Al + (size_t)(m0 + row) * lda + k0;
    const __nv_bfloat16* b  = Bh + (size_t)(n0 + row) * ldb + k0;
    const __nv_bfloat16* bl = Bl + (size_t)(n0 + row) * ldb + k0;
    #pragma unroll
    for (int i = 0; i < 2; i++) {
        int seg = qs * 2 + i;
        uint32_t sw = (uint32_t)((seg ^ (row & 7)) * 16);
        cp16(drow + sw,                   a + seg * 8);
        cp16(drow + sw + PLANE_BYTES,     al + seg * 8);
        cp16(drow + sw + 2 * PLANE_BYTES, b + seg * 8);
        cp16(drow + sw + 3 * PLANE_BYTES, bl + seg * 8);
    }
}

__device__ __forceinline__ void gemm_run(
    const __nv_bfloat16* __restrict__ Ah, const __nv_bfloat16* __restrict__ Al,
    const __nv_bfloat16* __restrict__ Bh, const __nv_bfloat16* __restrict__ Bl,
    int lda, int ldb, int K, int m0, int n0, float acc[2][4][4])
{
    extern __shared__ __align__(16) char smem[];
    uint32_t sb = smem_u32(smem);
    int tid = threadIdx.x, lane = tid & 31, warp = tid >> 5;
    int wm = (warp >> 2) * 32, wn = (warp & 3) * 32;
    int row = tid >> 2, qs = tid & 3;
    int g = lane >> 3, r = lane & 7;
    int rb = (g & 1) * 8 + r, hsel = g >> 1;

    int NC = K >> 6;
    // prologue: stages 0,1 in flight
    #pragma unroll
    for (int s = 0; s < NSTAGE - 1; s++) {
        load_stage(sb, s, row, qs, Ah, Al, Bh, Bl, lda, ldb, m0, n0, s * 64);
        CP_COMMIT();
    }

    uint32_t arow = (uint32_t)((wm + rb) * 128);
    uint32_t brow = (uint32_t)((wn + rb) * 128);

    for (int c = 0; c < NC; c++) {
        CP_WAIT1();              // group c retired (pending <= {c+1})
        __syncthreads();         // all warps done with slot (c+2)%3's prior data
        if (c + 2 < NC) {
            load_stage(sb, (c + 2) % NSTAGE, row, qs, Ah, Al, Bh, Bl,
                       lda, ldb, m0, n0, (c + 2) * 64);
            CP_COMMIT();
        }
        uint32_t st = sb + (uint32_t)(c % NSTAGE) * STAGE_BYTES;
        #pragma unroll
        for (int kb = 0; kb < 4; kb++) {
            uint32_t segoff = (uint32_t)((((kb * 2) | hsel) ^ r) * 16);
            uint32_t ah[2][4], al[2][4], bh[2][4], bl[2][4];
            #pragma unroll
            for (int mi = 0; mi < 2; mi++) {
                uint32_t ad = st + arow + (uint32_t)(mi * 16 * 128) + segoff;
                ldm4(ah[mi], ad);
                ldm4(al[mi], ad + PLANE_BYTES);
            }
            #pragma unroll
            for (int nb = 0; nb < 2; nb++) {
                uint32_t bd = st + 2 * PLANE_BYTES + brow + (uint32_t)(nb * 16 * 128) + segoff;
                ldm4(bh[nb], bd);
                ldm4(bl[nb], bd + PLANE_BYTES);
            }
            #pragma unroll
            for (int mi = 0; mi < 2; mi++)
                #pragma unroll
                for (int nb = 0; nb < 2; nb++)
                    #pragma unroll
                    for (int s = 0; s < 2; s++) {
                        int ni = nb * 2 + s;
                        mma16816(acc[mi][ni], ah[mi], bh[nb][s], bh[nb][s + 2]);
                        mma16816(acc[mi][ni], ah[mi], bl[nb][s], bl[nb][s + 2]);
                        mma16816(acc[mi][ni], al[mi], bh[nb][s], bh[nb][s + 2]);
                    }
        }
    }
}

// ======================= GEMM kernels =======================================
__global__ void __launch_bounds__(NTHREADS, 1) qkv_tc() {
    int z = blockIdx.z;
    const __nv_bfloat16* Bwh = g_Wh + (size_t)z * DMODEL * DMODEL;
    const __nv_bfloat16* Bwl = g_Wl + (size_t)z * DMODEL * DMODEL;
    int m0 = blockIdx.y * 128, n0 = blockIdx.x * 128;
    float acc[2][4][4] = {};
    gemm_run(g_Eh, g_El, Bwh, Bwl, DMODEL, DMODEL, DMODEL, m0, n0, acc);

    int lane = threadIdx.x & 31, warp = threadIdx.x >> 5;
    int wm = (warp >> 2) * 32, wn = (warp & 3) * 32;
    #pragma unroll
    for (int mi = 0; mi < 2; mi++)
        #pragma unroll
        for (int h = 0; h < 2; h++) {
            int rg = m0 + wm + mi * 16 + h * 8 + (lane >> 2);
            #pragma unroll
            for (int ni = 0; ni < 4; ni++) {
                int col = n0 + wn + ni * 8 + (lane & 3) * 2;
                unsigned short h0, h1, l0, l1;
                split_f32(acc[mi][ni][h * 2], h0, l0);
                split_f32(acc[mi][ni][h * 2 + 1], h1, l1);
                if (z == 2) {
                    int b = rg >> 11, s = rg & (SEQ - 1);
                    size_t vb = (size_t)b * DMODEL * SEQ;
                    g_Vth[vb + (size_t)col * SEQ + s] = __ushort_as_bfloat16(h0);
                    g_Vth[vb + (size_t)(col + 1) * SEQ + s] = __ushort_as_bfloat16(h1);
                    g_Vtl[vb + (size_t)col * SEQ + s] = __ushort_as_bfloat16(l0);
                    g_Vtl[vb + (size_t)(col + 1) * SEQ + s] = __ushort_as_bfloat16(l1);
                } else {
                    __nv_bfloat16* Ch = (z == 0) ? g_Qh : g_Kh;
                    __nv_bfloat16* Cl = (z == 0) ? g_Ql : g_Kl;
                    *(uint32_t*)&Ch[(size_t)rg * DMODEL + col] =
                        (uint32_t)h0 | ((uint32_t)h1 << 16);
                    *(uint32_t*)&Cl[(size_t)rg * DMODEL + col] =
                        (uint32_t)l0 | ((uint32_t)l1 << 16);
                }
            }
        }
}

__global__ void __launch_bounds__(NTHREADS, 1) scores_tc(
    const float* __restrict__ intent_bias, const int* __restrict__ mask,
    float* __restrict__ wts)
{
    int b = blockIdx.z;
    size_t off = (size_t)b * SEQ * DMODEL;
    int m0 = blockIdx.y * 128, n0 = blockIdx.x * 128;
    float acc[2][4][4] = {};
    gemm_run(g_Qh + off, g_Ql + off, g_Kh + off, g_Kl + off,
             DMODEL, DMODEL, DMODEL, m0, n0, acc);

    int lane = threadIdx.x & 31, warp = threadIdx.x >> 5;
    int wm = (warp >> 2) * 32, wn = (warp & 3) * 32;
    float th = g_thresh;
    float bias = intent_bias[0];
    #pragma unroll
    for (int mi = 0; mi < 2; mi++)
        #pragma unroll
        for (int h = 0; h < 2; h++) {
            int q = m0 + wm + mi * 16 + h * 8 + (lane >> 2);
            float mq = g_mags[b * SEQ + q];
            size_t rb = ((size_t)b * SEQ + q) * SEQ;
            #pragma unroll
            for (int ni = 0; ni < 4; ni++) {
                int col = n0 + wn + ni * 8 + (lane & 3) * 2;
                float x0 = acc[mi][ni][h * 2] * 0.03125f;
                float x1 = acc[mi][ni][h * 2 + 1] * 0.03125f;
                float mk0 = g_mags[b * SEQ + col];
                float mk1 = g_mags[b * SEQ + col + 1];
                if (mq * mk0 > th) x0 += bias;
                if (mq * mk1 > th) x1 += bias;
                int2 mv = *(const int2*)&mask[rb + col];
                if (mv.x == 0) x0 = -1e9f;
                if (mv.y == 0) x1 = -1e9f;
                *(float2*)&wts[rb + col] = make_float2(x0, x1);
            }
        }
}

__global__ void __launch_bounds__(NTHREADS, 1) av_tc(float* __restrict__ att) {
    int b = blockIdx.z;
    size_t po = (size_t)b * SEQ * SEQ;
    size_t vo = (size_t)b * DMODEL * SEQ;
    int m0 = blockIdx.y * 128, n0 = blockIdx.x * 128;
    float acc[2][4][4] = {};
    gemm_run(g_Ph + po, g_Pl + po, g_Vth + vo, g_Vtl + vo,
             SEQ, SEQ, SEQ, m0, n0, acc);

    int lane = threadIdx.x & 31, warp = threadIdx.x >> 5;
    int wm = (warp >> 2) * 32, wn = (warp & 3) * 32;
    #pragma unroll
    for (int mi = 0; mi < 2; mi++)
        #pragma unroll
        for (int h = 0; h < 2; h++) {
            int s = m0 + wm + mi * 16 + h * 8 + (lane >> 2);
            #pragma unroll
            for (int ni = 0; ni < 4; ni++) {
                int col = n0 + wn + ni * 8 + (lane & 3) * 2;
                *(float2*)&att[((size_t)b * SEQ + s) * DMODEL + col] =
                    make_float2(acc[mi][ni][h * 2], acc[mi][ni][h * 2 + 1]);
            }
        }
}

// ======================= launch =============================================
extern "C" void kernel_launch(void* const* d_in, const int* in_sizes, int n_in,
                              void* d_out, int out_size)
{
    (void)in_sizes; (void)n_in; (void)out_size;
    const float* E    = (const float*)d_in[0];
    const float* Wq   = (const float*)d_in[1];
    const float* Wk   = (const float*)d_in[2];
    const float* Wv   = (const float*)d_in[3];
    const float* bias = (const float*)d_in[4];
    const int*   mask = (const int*)d_in[5];

    float* out = (float*)d_out;
    float* att = out;                                  // [B,S,D]
    float* wts = out + (size_t)BATCH * SEQ * DMODEL;   // [B,S,S]

    cudaFuncSetAttribute(qkv_tc,    cudaFuncAttributeMaxDynamicSharedMemorySize, SMEM_TOTAL);
    cudaFuncSetAttribute(scores_tc, cudaFuncAttributeMaxDynamicSharedMemorySize, SMEM_TOTAL);
    cudaFuncSetAttribute(av_tc,     cudaFuncAttributeMaxDynamicSharedMemorySize, SMEM_TOTAL);

    int ntot = NE4 + 3 * NW4;
    convert_all<<<(ntot + 255) / 256, 256>>>(E, Wq, Wk, Wv);

    mags_kernel<<<BATCH * SEQ, 256>>>(E);
    thresh_kernel<<<1, 256>>>();

    dim3 gQKV(DMODEL / 128, (BATCH * SEQ) / 128, 3);
    qkv_tc<<<gQKV, NTHREADS, SMEM_TOTAL>>>();

    dim3 gS(SEQ / 128, SEQ / 128, BATCH);
    scores_tc<<<gS, NTHREADS, SMEM_TOTAL>>>(bias, mask, wts);

    softmax_kernel<<<BATCH * SEQ, 256>>>(wts);

    dim3 gAV(DMODEL / 128, SEQ / 128, BATCH);
    av_tc<<<gAV, NTHREADS, SMEM_TOTAL>>>(att);
}